// round 1
// baseline (speedup 1.0000x reference)
#include <cuda_runtime.h>
#include <cstdint>

#define NMAX 50000
#define EMAX 1600000

// ---------------- scratch (static __device__, no allocations) ----------------
__device__ float  g_hm[NMAX * 32];      // h @ lin_W[:32]  per node
__device__ float2 g_ai[NMAX];           // h @ att_W[0:32]   (dst term)
__device__ float2 g_aj[NMAX];           // h @ att_W[32:64]  (src term)
__device__ float  g_denom[NMAX * 2];    // softmax denominators per (node, head)
__device__ float2 g_e2[EMAX];           // exp(alpha) per edge (orig order)
__device__ float2 g_e2c[EMAX];          // exp(alpha) in CSR order
__device__ uint4  g_rec[EMAX];          // CSR records {eid, src, dst, pad}
__device__ int    g_cnt[NMAX];
__device__ int    g_scan[NMAX];
__device__ int    g_rowptr[NMAX];
__device__ int    g_cur[NMAX];
__device__ int    g_bsum[128];
__device__ int    g_boff[128];
__device__ float  g_ae[8];              // lrelu(etype_table) @ att_W[64:80]
__device__ float  g_acc[NMAX * 64];     // output accumulator

__device__ __forceinline__ float lrelu(float v) { return v > 0.f ? v : 0.2f * v; }

// ---------------- K0: zero scratch ----------------
__global__ void k_zero(int n) {
    int i = blockIdx.x * 256 + threadIdx.x;
    int tot = n * 64;
    if (i < tot) g_acc[i] = 0.f;
    if (i < 2 * n) g_denom[i] = 0.f;
    if (i < n) { g_cnt[i] = 0; g_cur[i] = 0; }
}

// ---------------- K1: node precompute (warp per node) ----------------
__global__ __launch_bounds__(256) void k_node(
    const float* __restrict__ x, const int* __restrict__ ntypes,
    const float* __restrict__ hetW, const float* __restrict__ hetB,
    const float* __restrict__ attW, const float* __restrict__ linW, int n)
{
    __shared__ float sx[8][128];
    __shared__ float sh[8][32];
    int w = threadIdx.x >> 5, lane = threadIdx.x & 31;
    int node = blockIdx.x * 8 + w;
    if (node >= n) return;

    const float4* xr = (const float4*)(x + (size_t)node * 128);
    ((float4*)sx[w])[lane] = xr[lane];
    __syncwarp();

    int t = ntypes[node];
    const float* Wp = hetW + (size_t)t * 4096 + lane;
    float acc = hetB[t * 32 + lane];
#pragma unroll 16
    for (int d = 0; d < 128; ++d) acc += sx[w][d] * Wp[d * 32];
    float h = acc;
    sh[w][lane] = h;
    __syncwarp();

    // hm = h @ lin_W[0:32, :]
    float hm = 0.f;
#pragma unroll
    for (int k = 0; k < 32; ++k) hm += sh[w][k] * linW[k * 32 + lane];
    g_hm[(size_t)node * 32 + lane] = hm;

    // attention partials: a_i = h @ att_W[0:32], a_j = h @ att_W[32:64]
    float pi0 = h * attW[lane * 2 + 0];
    float pi1 = h * attW[lane * 2 + 1];
    float pj0 = h * attW[(32 + lane) * 2 + 0];
    float pj1 = h * attW[(32 + lane) * 2 + 1];
#pragma unroll
    for (int off = 16; off; off >>= 1) {
        pi0 += __shfl_down_sync(0xffffffffu, pi0, off);
        pi1 += __shfl_down_sync(0xffffffffu, pi1, off);
        pj0 += __shfl_down_sync(0xffffffffu, pj0, off);
        pj1 += __shfl_down_sync(0xffffffffu, pj1, off);
    }
    if (lane == 0) {
        g_ai[node] = make_float2(pi0, pi1);
        g_aj[node] = make_float2(pj0, pj1);
    }
}

// ---------------- K1b: per-etype attention term ----------------
__global__ void k_ae(const float* __restrict__ ett, const float* __restrict__ attW) {
    int tid = threadIdx.x;
    if (tid < 8) {
        int t = tid >> 1, hh = tid & 1;
        float s = 0.f;
        for (int k = 0; k < 16; ++k)
            s += lrelu(ett[t * 16 + k]) * attW[(64 + k) * 2 + hh];
        g_ae[tid] = s;
    }
}

// ---------------- K2: edge pass 1 — exp(alpha), denom, degree histogram ----------------
__global__ __launch_bounds__(256) void k_edge1(
    const int* __restrict__ ei, const int* __restrict__ etypes,
    const float* __restrict__ eattr, const float* __restrict__ cW,
    const float* __restrict__ attW, int e_total)
{
    __shared__ float scW[256], saW2[32], sae[8];
    int tid = threadIdx.x;
    scW[tid] = cW[tid];
    if (tid < 32) saW2[tid] = attW[160 + tid];   // rows 80..95
    if (tid < 8)  sae[tid] = g_ae[tid];
    __syncthreads();

    int e = blockIdx.x * 256 + tid;
    if (e >= e_total) return;
    int src = ei[e], dst = ei[e_total + e], et = etypes[e];

    const float4* er = (const float4*)(eattr + (size_t)e * 16);
    float4 q0 = er[0], q1 = er[1], q2 = er[2], q3 = er[3];
    float va[16] = {q0.x, q0.y, q0.z, q0.w, q1.x, q1.y, q1.z, q1.w,
                    q2.x, q2.y, q2.z, q2.w, q3.x, q3.y, q3.z, q3.w};

    float ea[16];
#pragma unroll
    for (int k = 0; k < 16; ++k) {
        float s = 0.f;
#pragma unroll
        for (int d = 0; d < 16; ++d) s += va[d] * scW[d * 16 + k];
        ea[k] = lrelu(s);
    }

    float2 fi = g_ai[dst], fj = g_aj[src];
    float a0 = fi.x + fj.x + sae[et * 2 + 0];
    float a1 = fi.y + fj.y + sae[et * 2 + 1];
#pragma unroll
    for (int k = 0; k < 16; ++k) {
        a0 += ea[k] * saW2[k * 2 + 0];
        a1 += ea[k] * saW2[k * 2 + 1];
    }
    a0 = lrelu(a0); a1 = lrelu(a1);
    float e0 = __expf(a0), e1 = __expf(a1);

    g_e2[e] = make_float2(e0, e1);
    atomicAdd(&g_denom[dst * 2 + 0], e0);
    atomicAdd(&g_denom[dst * 2 + 1], e1);
    atomicAdd(&g_cnt[dst], 1);
}

// ---------------- K3: exclusive scan of degree counts (3 kernels) ----------------
__global__ void k_scan1(int n) {
    __shared__ int s[1024];
    int i = blockIdx.x * 1024 + threadIdx.x;
    int v = (i < n) ? g_cnt[i] : 0;
    s[threadIdx.x] = v;
    __syncthreads();
    for (int off = 1; off < 1024; off <<= 1) {
        int t = (threadIdx.x >= off) ? s[threadIdx.x - off] : 0;
        __syncthreads();
        s[threadIdx.x] += t;
        __syncthreads();
    }
    if (i < n) g_scan[i] = s[threadIdx.x];
    if (threadIdx.x == 1023) g_bsum[blockIdx.x] = s[1023];
}
__global__ void k_scan2(int nb) {
    if (threadIdx.x == 0) {
        int run = 0;
        for (int b = 0; b < nb; ++b) { g_boff[b] = run; run += g_bsum[b]; }
    }
}
__global__ void k_scan3(int n) {
    int i = blockIdx.x * 1024 + threadIdx.x;
    if (i < n) g_rowptr[i] = g_scan[i] - g_cnt[i] + g_boff[blockIdx.x];
}

// ---------------- K4: CSR fill ----------------
__global__ __launch_bounds__(256) void k_fill(const int* __restrict__ ei, int e_total) {
    int e = blockIdx.x * 256 + threadIdx.x;
    if (e >= e_total) return;
    int src = ei[e], dst = ei[e_total + e];
    int pos = g_rowptr[dst] + atomicAdd(&g_cur[dst], 1);
    g_rec[pos] = make_uint4((unsigned)e, (unsigned)src, (unsigned)dst, 0u);
    g_e2c[pos] = g_e2[e];
}

// ---------------- K5: edge pass 2 — message + softmax-weighted segmented scatter ----------------
__global__ __launch_bounds__(256) void k_edge2(
    const float* __restrict__ eattr, const float* __restrict__ cW,
    const float* __restrict__ linW, int e_total)
{
    __shared__ float scW[256], slW2[512];
    int tid = threadIdx.x;
    scW[tid] = cW[tid];
    slW2[tid] = linW[1024 + tid];         // lin_W rows 32..39
    slW2[256 + tid] = linW[1280 + tid];   // lin_W rows 40..47
    __syncthreads();

    int i = blockIdx.x * 256 + tid;
    bool valid = i < e_total;
    int ii = valid ? i : (e_total - 1);

    uint4 rec = g_rec[ii];
    int eid = (int)rec.x;
    int src = (int)rec.y;
    int dst = valid ? (int)rec.z : 0;
    int dseg = valid ? (int)rec.z : 0x7FFFFFFF;   // sentinel segment for inactive lanes

    float2 ex = g_e2c[ii];
    float d0 = g_denom[dst * 2 + 0];
    float d1 = g_denom[dst * 2 + 1];
    float w0 = valid ? ex.x / d0 : 0.f;
    float w1 = valid ? ex.y / d1 : 0.f;

    const float4* er = (const float4*)(eattr + (size_t)eid * 16);
    float4 q0 = er[0], q1 = er[1], q2 = er[2], q3 = er[3];
    float va[16] = {q0.x, q0.y, q0.z, q0.w, q1.x, q1.y, q1.z, q1.w,
                    q2.x, q2.y, q2.z, q2.w, q3.x, q3.y, q3.z, q3.w};

    float ea[16];
#pragma unroll
    for (int k = 0; k < 16; ++k) {
        float s = 0.f;
#pragma unroll
        for (int d = 0; d < 16; ++d) s += va[d] * scW[d * 16 + k];
        ea[k] = lrelu(s);
    }

    const float4* hr = (const float4*)(g_hm + (size_t)src * 32);
    float4 hv0 = hr[0], hv1 = hr[1], hv2 = hr[2], hv3 = hr[3];
    float4 hv4 = hr[4], hv5 = hr[5], hv6 = hr[6], hv7 = hr[7];
    float hmv[32] = {hv0.x, hv0.y, hv0.z, hv0.w, hv1.x, hv1.y, hv1.z, hv1.w,
                     hv2.x, hv2.y, hv2.z, hv2.w, hv3.x, hv3.y, hv3.z, hv3.w,
                     hv4.x, hv4.y, hv4.z, hv4.w, hv5.x, hv5.y, hv5.z, hv5.w,
                     hv6.x, hv6.y, hv6.z, hv6.w, hv7.x, hv7.y, hv7.z, hv7.w};

    // warp segmentation (edges sorted by dst)
    int lane = tid & 31;
    int dprev = __shfl_up_sync(0xffffffffu, dseg, 1);
    bool head = (lane == 0) || (dprev != dseg);
    unsigned hb = __ballot_sync(0xffffffffu, head);
    unsigned above = hb & (0xFFFFFFFEu << lane);
    int segend = above ? (__ffs(above) - 2) : 31;

#pragma unroll
    for (int c = 0; c < 32; ++c) {
        float m = hmv[c];
#pragma unroll
        for (int k = 0; k < 16; ++k) m += ea[k] * slW2[k * 32 + c];
        float v0 = w0 * m, v1 = w1 * m;
#pragma unroll
        for (int off = 1; off < 32; off <<= 1) {
            float o0 = __shfl_down_sync(0xffffffffu, v0, off);
            float o1 = __shfl_down_sync(0xffffffffu, v1, off);
            if (lane + off <= segend) { v0 += o0; v1 += o1; }
        }
        if (head && valid) {
            atomicAdd(&g_acc[(size_t)dst * 64 + c], v0);
            atomicAdd(&g_acc[(size_t)dst * 64 + 32 + c], v1);
        }
    }
}

// ---------------- K6: final relu -> out ----------------
__global__ void k_out(float* __restrict__ out, int total) {
    int i = blockIdx.x * 256 + threadIdx.x;
    if (i < total) out[i] = fmaxf(g_acc[i], 0.f);
}

// ---------------- launch ----------------
extern "C" void kernel_launch(void* const* d_in, const int* in_sizes, int n_in,
                              void* d_out, int out_size)
{
    const float* x      = (const float*)d_in[0];
    const int*   ei     = (const int*)  d_in[1];
    const int*   ntypes = (const int*)  d_in[2];
    const int*   etypes = (const int*)  d_in[3];
    const float* eattr  = (const float*)d_in[4];
    const float* hetW   = (const float*)d_in[5];
    const float* hetB   = (const float*)d_in[6];
    const float* ett    = (const float*)d_in[7];
    const float* cW     = (const float*)d_in[8];
    const float* attW   = (const float*)d_in[9];
    const float* linW   = (const float*)d_in[10];

    int n = in_sizes[0] / 128;
    int e = in_sizes[1] / 2;
    if (n > NMAX) n = NMAX;
    if (e > EMAX) e = EMAX;

    k_zero<<<(n * 64 + 255) / 256, 256>>>(n);
    k_node<<<(n + 7) / 8, 256>>>(x, ntypes, hetW, hetB, attW, linW, n);
    k_ae<<<1, 32>>>(ett, attW);
    k_edge1<<<(e + 255) / 256, 256>>>(ei, etypes, eattr, cW, attW, e);

    int nb = (n + 1023) / 1024;
    k_scan1<<<nb, 1024>>>(n);
    k_scan2<<<1, 32>>>(nb);
    k_scan3<<<nb, 1024>>>(n);

    k_fill<<<(e + 255) / 256, 256>>>(ei, e);
    k_edge2<<<(e + 255) / 256, 256>>>(eattr, cW, linW, e);
    k_out<<<(n * 64 + 255) / 256, 256>>>((float*)d_out, n * 64);
}

// round 2
// speedup vs baseline: 1.2399x; 1.2399x over previous
#include <cuda_runtime.h>
#include <cstdint>

#define NMAX 50000
#define EMAX 1600000

// ---------------- scratch (static __device__, no allocations) ----------------
__device__ float  g_hm[NMAX * 32];        // h @ lin_W[0:32]  per node (L2-resident, 6.4MB)
__device__ float2 g_ai[NMAX];             // h @ att_W[0:32]   (dst term)
__device__ float2 g_aj[NMAX];             // h @ att_W[32:64]  (src term)
__device__ float  g_denom[NMAX * 2];      // softmax denominators per (node, head)
__device__ int    g_srcc[EMAX];           // src node per edge, CSR(dst) order
__device__ float2 g_e2c[EMAX];            // exp(alpha) per edge, CSR order
__device__ float  g_em[(size_t)EMAX * 32];// ea @ lin_W[32:48] per edge, CSR order (205MB)
__device__ int    g_cnt[NMAX];
__device__ int    g_scan[NMAX];
__device__ int    g_rowptr[NMAX];
__device__ int    g_cur[NMAX];
__device__ int    g_bsum[128];
__device__ int    g_boff[128];
__device__ float  g_ae[8];                // lrelu(etype_table) @ att_W[64:80]

__device__ __forceinline__ float lrelu(float v) { return v > 0.f ? v : 0.2f * v; }

// ---------------- K0: zero counters ----------------
__global__ void k_zero(int n) {
    int i = blockIdx.x * 256 + threadIdx.x;
    if (i < 2 * n) g_denom[i] = 0.f;
    if (i < n) { g_cnt[i] = 0; g_cur[i] = 0; }
}

// ---------------- K1: node precompute (warp per node) ----------------
__global__ __launch_bounds__(256) void k_node(
    const float* __restrict__ x, const int* __restrict__ ntypes,
    const float* __restrict__ hetW, const float* __restrict__ hetB,
    const float* __restrict__ attW, const float* __restrict__ linW, int n)
{
    __shared__ float sx[8][128];
    __shared__ float sh[8][32];
    int w = threadIdx.x >> 5, lane = threadIdx.x & 31;
    int node = blockIdx.x * 8 + w;
    if (node >= n) return;

    const float4* xr = (const float4*)(x + (size_t)node * 128);
    ((float4*)sx[w])[lane] = xr[lane];
    __syncwarp();

    int t = ntypes[node];
    const float* Wp = hetW + (size_t)t * 4096 + lane;
    float acc = hetB[t * 32 + lane];
#pragma unroll 16
    for (int d = 0; d < 128; ++d) acc += sx[w][d] * Wp[d * 32];
    float h = acc;
    sh[w][lane] = h;
    __syncwarp();

    // hm = h @ lin_W[0:32, :]
    float hm = 0.f;
#pragma unroll
    for (int k = 0; k < 32; ++k) hm += sh[w][k] * linW[k * 32 + lane];
    g_hm[(size_t)node * 32 + lane] = hm;

    // attention partials
    float pi0 = h * attW[lane * 2 + 0];
    float pi1 = h * attW[lane * 2 + 1];
    float pj0 = h * attW[(32 + lane) * 2 + 0];
    float pj1 = h * attW[(32 + lane) * 2 + 1];
#pragma unroll
    for (int off = 16; off; off >>= 1) {
        pi0 += __shfl_down_sync(0xffffffffu, pi0, off);
        pi1 += __shfl_down_sync(0xffffffffu, pi1, off);
        pj0 += __shfl_down_sync(0xffffffffu, pj0, off);
        pj1 += __shfl_down_sync(0xffffffffu, pj1, off);
    }
    if (lane == 0) {
        g_ai[node] = make_float2(pi0, pi1);
        g_aj[node] = make_float2(pj0, pj1);
    }
}

// ---------------- K1b: per-etype attention term ----------------
__global__ void k_ae(const float* __restrict__ ett, const float* __restrict__ attW) {
    int tid = threadIdx.x;
    if (tid < 8) {
        int t = tid >> 1, hh = tid & 1;
        float s = 0.f;
        for (int k = 0; k < 16; ++k)
            s += lrelu(ett[t * 16 + k]) * attW[(64 + k) * 2 + hh];
        g_ae[tid] = s;
    }
}

// ---------------- K2: degree histogram ----------------
__global__ void k_cnt(const int* __restrict__ ei, int e_total) {
    int e = blockIdx.x * 256 + threadIdx.x;
    if (e < e_total) atomicAdd(&g_cnt[ei[e_total + e]], 1);
}

// ---------------- K3: exclusive scan of degree counts ----------------
__global__ void k_scan1(int n) {
    __shared__ int s[1024];
    int i = blockIdx.x * 1024 + threadIdx.x;
    int v = (i < n) ? g_cnt[i] : 0;
    s[threadIdx.x] = v;
    __syncthreads();
    for (int off = 1; off < 1024; off <<= 1) {
        int t = (threadIdx.x >= off) ? s[threadIdx.x - off] : 0;
        __syncthreads();
        s[threadIdx.x] += t;
        __syncthreads();
    }
    if (i < n) g_scan[i] = s[threadIdx.x];
    if (threadIdx.x == 1023) g_bsum[blockIdx.x] = s[1023];
}
__global__ void k_scan2(int nb) {
    if (threadIdx.x == 0) {
        int run = 0;
        for (int b = 0; b < nb; ++b) { g_boff[b] = run; run += g_bsum[b]; }
    }
}
__global__ void k_scan3(int n) {
    int i = blockIdx.x * 1024 + threadIdx.x;
    if (i < n) g_rowptr[i] = g_scan[i] - g_cnt[i] + g_boff[blockIdx.x];
}

// ---------------- K4: edge pass — ea, alpha, exp, em; write in CSR order ----------------
__global__ __launch_bounds__(256) void k_edge1(
    const int* __restrict__ ei, const int* __restrict__ etypes,
    const float* __restrict__ eattr, const float* __restrict__ cW,
    const float* __restrict__ attW, const float* __restrict__ linW, int e_total)
{
    __shared__ float4 scW4[64];    // eattr_W [16,16] as float4 rows
    __shared__ float4 slW4[128];   // lin_W rows 32..47 [16,32] as float4
    __shared__ float2 saW2[16];    // att_W rows 80..95 [16,2]
    __shared__ float  sae[8];
    int tid = threadIdx.x;
    if (tid < 64) scW4[tid] = ((const float4*)cW)[tid];
    else if (tid < 192) slW4[tid - 64] = ((const float4*)(linW + 1024))[tid - 64];
    else if (tid < 208) saW2[tid - 192] = ((const float2*)(attW + 160))[tid - 192];
    else if (tid < 216) sae[tid - 208] = g_ae[tid - 208];
    __syncthreads();

    int e = blockIdx.x * 256 + tid;
    if (e >= e_total) return;
    int src = ei[e], dst = ei[e_total + e], et = etypes[e];

    const float4* er = (const float4*)(eattr + (size_t)e * 16);
    float4 q0 = er[0], q1 = er[1], q2 = er[2], q3 = er[3];
    float va[16] = {q0.x, q0.y, q0.z, q0.w, q1.x, q1.y, q1.z, q1.w,
                    q2.x, q2.y, q2.z, q2.w, q3.x, q3.y, q3.z, q3.w};

    float ea[16];
#pragma unroll
    for (int k = 0; k < 16; ++k) ea[k] = 0.f;
#pragma unroll
    for (int d = 0; d < 16; ++d) {
        float vd = va[d];
#pragma unroll
        for (int k4 = 0; k4 < 4; ++k4) {
            float4 w = scW4[d * 4 + k4];
            ea[k4 * 4 + 0] += vd * w.x;
            ea[k4 * 4 + 1] += vd * w.y;
            ea[k4 * 4 + 2] += vd * w.z;
            ea[k4 * 4 + 3] += vd * w.w;
        }
    }
#pragma unroll
    for (int k = 0; k < 16; ++k) ea[k] = lrelu(ea[k]);

    // attention logits -> exp
    float2 fi = g_ai[dst], fj = g_aj[src];
    float a0 = fi.x + fj.x + sae[et * 2 + 0];
    float a1 = fi.y + fj.y + sae[et * 2 + 1];
#pragma unroll
    for (int k = 0; k < 16; ++k) {
        float2 w = saW2[k];
        a0 += ea[k] * w.x;
        a1 += ea[k] * w.y;
    }
    float e0 = __expf(lrelu(a0));
    float e1 = __expf(lrelu(a1));

    // claim CSR slot
    int pos = g_rowptr[dst] + atomicAdd(&g_cur[dst], 1);
    g_srcc[pos] = src;
    g_e2c[pos] = make_float2(e0, e1);
    atomicAdd(&g_denom[dst * 2 + 0], e0);
    atomicAdd(&g_denom[dst * 2 + 1], e1);

    // em = ea @ lin_W[32:48, :]  -> CSR-ordered edge message
    float4* emp = (float4*)(g_em + (size_t)pos * 32);
#pragma unroll
    for (int cc = 0; cc < 8; ++cc) {
        float4 acc = make_float4(0.f, 0.f, 0.f, 0.f);
#pragma unroll
        for (int k = 0; k < 16; ++k) {
            float4 w = slW4[k * 8 + cc];
            acc.x += ea[k] * w.x;
            acc.y += ea[k] * w.y;
            acc.z += ea[k] * w.z;
            acc.w += ea[k] * w.w;
        }
        emp[cc] = acc;
    }
}

// ---------------- K5: aggregate — warp per dst node, streaming CSR ----------------
__global__ __launch_bounds__(256) void k_edge2(float* __restrict__ out, int n)
{
    int w = blockIdx.x * 8 + (threadIdx.x >> 5);
    if (w >= n) return;
    int lane = threadIdx.x & 31;
    int beg = g_rowptr[w];
    int cnt = g_cnt[w];

    const int*    sc  = g_srcc + beg;
    const float2* exc = g_e2c + beg;
    const float*  emb = g_em + (size_t)beg * 32;

    float acc0 = 0.f, acc1 = 0.f;
    int p = 0;
    for (; p + 4 <= cnt; p += 4) {
        int s0 = sc[p], s1 = sc[p + 1], s2 = sc[p + 2], s3 = sc[p + 3];
        float2 x0 = exc[p], x1 = exc[p + 1], x2 = exc[p + 2], x3 = exc[p + 3];
        float m0 = g_hm[(size_t)s0 * 32 + lane] + emb[(size_t)(p + 0) * 32 + lane];
        float m1 = g_hm[(size_t)s1 * 32 + lane] + emb[(size_t)(p + 1) * 32 + lane];
        float m2 = g_hm[(size_t)s2 * 32 + lane] + emb[(size_t)(p + 2) * 32 + lane];
        float m3 = g_hm[(size_t)s3 * 32 + lane] + emb[(size_t)(p + 3) * 32 + lane];
        acc0 += x0.x * m0 + x1.x * m1 + x2.x * m2 + x3.x * m3;
        acc1 += x0.y * m0 + x1.y * m1 + x2.y * m2 + x3.y * m3;
    }
    for (; p < cnt; ++p) {
        int s = sc[p];
        float2 x = exc[p];
        float m = g_hm[(size_t)s * 32 + lane] + emb[(size_t)p * 32 + lane];
        acc0 += x.x * m;
        acc1 += x.y * m;
    }

    float2 den = ((const float2*)g_denom)[w];
    float i0 = (den.x != 0.f) ? 1.f / den.x : 0.f;
    float i1 = (den.y != 0.f) ? 1.f / den.y : 0.f;
    out[(size_t)w * 64 + lane]      = fmaxf(acc0 * i0, 0.f);
    out[(size_t)w * 64 + 32 + lane] = fmaxf(acc1 * i1, 0.f);
}

// ---------------- launch ----------------
extern "C" void kernel_launch(void* const* d_in, const int* in_sizes, int n_in,
                              void* d_out, int out_size)
{
    const float* x      = (const float*)d_in[0];
    const int*   ei     = (const int*)  d_in[1];
    const int*   ntypes = (const int*)  d_in[2];
    const int*   etypes = (const int*)  d_in[3];
    const float* eattr  = (const float*)d_in[4];
    const float* hetW   = (const float*)d_in[5];
    const float* hetB   = (const float*)d_in[6];
    const float* ett    = (const float*)d_in[7];
    const float* cW     = (const float*)d_in[8];
    const float* attW   = (const float*)d_in[9];
    const float* linW   = (const float*)d_in[10];

    int n = in_sizes[0] / 128;
    int e = in_sizes[1] / 2;
    if (n > NMAX) n = NMAX;
    if (e > EMAX) e = EMAX;

    k_zero<<<(2 * n + 255) / 256, 256>>>(n);
    k_node<<<(n + 7) / 8, 256>>>(x, ntypes, hetW, hetB, attW, linW, n);
    k_ae<<<1, 32>>>(ett, attW);
    k_cnt<<<(e + 255) / 256, 256>>>(ei, e);

    int nb = (n + 1023) / 1024;
    k_scan1<<<nb, 1024>>>(n);
    k_scan2<<<1, 32>>>(nb);
    k_scan3<<<nb, 1024>>>(n);

    k_edge1<<<(e + 255) / 256, 256>>>(ei, etypes, eattr, cW, attW, linW, e);
    k_edge2<<<(n + 7) / 8, 256>>>((float*)d_out, n);
}

// round 3
// speedup vs baseline: 1.5961x; 1.2873x over previous
#include <cuda_runtime.h>
#include <cstdint>

#define NMAX 50000
#define EMAX 1600000
#define RECF 20   // floats per CSR record: src,e0,e1,ea[16],pad

// ---------------- scratch (static __device__, no allocations) ----------------
__device__ float  g_hm[NMAX * 32];          // h @ lin_W[0:32] per node (6.4MB, L2-resident)
__device__ float2 g_ai[NMAX];               // h @ att_W[0:32]  (dst term)
__device__ float2 g_aj[NMAX];               // h @ att_W[32:64] (src term)
__device__ float  g_rec[(size_t)EMAX * RECF]; // CSR records (128MB)
__device__ int    g_cnt[NMAX];
__device__ int    g_scan[NMAX];
__device__ int    g_rowptr[NMAX];
__device__ int    g_cur[NMAX];
__device__ int    g_bsum[128];
__device__ int    g_boff[128];
__device__ float  g_ae[8];                  // lrelu(etype_table) @ att_W[64:80]

__device__ __forceinline__ float lrelu(float v) { return v > 0.f ? v : 0.2f * v; }

// ---------------- K0: zero counters ----------------
__global__ void k_zero(int n) {
    int i = blockIdx.x * 256 + threadIdx.x;
    if (i < n) { g_cnt[i] = 0; g_cur[i] = 0; }
}

// ---------------- K1: node precompute (warp per node) ----------------
__global__ __launch_bounds__(256) void k_node(
    const float* __restrict__ x, const int* __restrict__ ntypes,
    const float* __restrict__ hetW, const float* __restrict__ hetB,
    const float* __restrict__ attW, const float* __restrict__ linW, int n)
{
    __shared__ float sx[8][128];
    __shared__ float sh[8][32];
    int w = threadIdx.x >> 5, lane = threadIdx.x & 31;
    int node = blockIdx.x * 8 + w;
    if (node >= n) return;

    const float4* xr = (const float4*)(x + (size_t)node * 128);
    ((float4*)sx[w])[lane] = xr[lane];
    __syncwarp();

    int t = ntypes[node];
    const float* Wp = hetW + (size_t)t * 4096 + lane;
    float acc = hetB[t * 32 + lane];
#pragma unroll 16
    for (int d = 0; d < 128; ++d) acc += sx[w][d] * Wp[d * 32];
    float h = acc;
    sh[w][lane] = h;
    __syncwarp();

    float hm = 0.f;
#pragma unroll
    for (int k = 0; k < 32; ++k) hm += sh[w][k] * linW[k * 32 + lane];
    g_hm[(size_t)node * 32 + lane] = hm;

    float pi0 = h * attW[lane * 2 + 0];
    float pi1 = h * attW[lane * 2 + 1];
    float pj0 = h * attW[(32 + lane) * 2 + 0];
    float pj1 = h * attW[(32 + lane) * 2 + 1];
#pragma unroll
    for (int off = 16; off; off >>= 1) {
        pi0 += __shfl_down_sync(0xffffffffu, pi0, off);
        pi1 += __shfl_down_sync(0xffffffffu, pi1, off);
        pj0 += __shfl_down_sync(0xffffffffu, pj0, off);
        pj1 += __shfl_down_sync(0xffffffffu, pj1, off);
    }
    if (lane == 0) {
        g_ai[node] = make_float2(pi0, pi1);
        g_aj[node] = make_float2(pj0, pj1);
    }
}

// ---------------- K1b: per-etype attention term ----------------
__global__ void k_ae(const float* __restrict__ ett, const float* __restrict__ attW) {
    int tid = threadIdx.x;
    if (tid < 8) {
        int t = tid >> 1, hh = tid & 1;
        float s = 0.f;
        for (int k = 0; k < 16; ++k)
            s += lrelu(ett[t * 16 + k]) * attW[(64 + k) * 2 + hh];
        g_ae[tid] = s;
    }
}

// ---------------- K2: degree histogram (vectorized) ----------------
__global__ void k_cnt(const int* __restrict__ dst, int e_total) {
    int i = blockIdx.x * 256 + threadIdx.x;
    int base = i * 4;
    if (base + 4 <= e_total) {
        int4 d = *(const int4*)(dst + base);
        atomicAdd(&g_cnt[d.x], 1);
        atomicAdd(&g_cnt[d.y], 1);
        atomicAdd(&g_cnt[d.z], 1);
        atomicAdd(&g_cnt[d.w], 1);
    } else {
        for (int e = base; e < e_total; ++e) atomicAdd(&g_cnt[dst[e]], 1);
    }
}

// ---------------- K3: exclusive scan of degree counts ----------------
__global__ void k_scan1(int n) {
    __shared__ int s[1024];
    int i = blockIdx.x * 1024 + threadIdx.x;
    int v = (i < n) ? g_cnt[i] : 0;
    s[threadIdx.x] = v;
    __syncthreads();
    for (int off = 1; off < 1024; off <<= 1) {
        int t = (threadIdx.x >= off) ? s[threadIdx.x - off] : 0;
        __syncthreads();
        s[threadIdx.x] += t;
        __syncthreads();
    }
    if (i < n) g_scan[i] = s[threadIdx.x];
    if (threadIdx.x == 1023) g_bsum[blockIdx.x] = s[1023];
}
__global__ void k_scan2(int nb) {
    if (threadIdx.x == 0) {
        int run = 0;
        for (int b = 0; b < nb; ++b) { g_boff[b] = run; run += g_bsum[b]; }
    }
}
__global__ void k_scan3(int n) {
    int i = blockIdx.x * 1024 + threadIdx.x;
    if (i < n) g_rowptr[i] = g_scan[i] - g_cnt[i] + g_boff[blockIdx.x];
}

// ---------------- K4: edge pass — ea, exp(alpha); scatter record in CSR order ----------------
__global__ __launch_bounds__(256) void k_edge1(
    const int* __restrict__ ei, const int* __restrict__ etypes,
    const float* __restrict__ eattr, const float* __restrict__ cW,
    const float* __restrict__ attW, int e_total)
{
    __shared__ float4 scW4[64];    // eattr_W [16,16] as float4 rows
    __shared__ float2 saW2[16];    // att_W rows 80..95 [16,2]
    __shared__ float  sae[8];
    int tid = threadIdx.x;
    if (tid < 64) scW4[tid] = ((const float4*)cW)[tid];
    else if (tid < 80) saW2[tid - 64] = ((const float2*)(attW + 160))[tid - 64];
    else if (tid < 88) sae[tid - 80] = g_ae[tid - 80];
    __syncthreads();

    int e = blockIdx.x * 256 + tid;
    if (e >= e_total) return;
    int src = ei[e], dst = ei[e_total + e], et = etypes[e];

    const float4* er = (const float4*)(eattr + (size_t)e * 16);
    float4 q0 = er[0], q1 = er[1], q2 = er[2], q3 = er[3];
    float va[16] = {q0.x, q0.y, q0.z, q0.w, q1.x, q1.y, q1.z, q1.w,
                    q2.x, q2.y, q2.z, q2.w, q3.x, q3.y, q3.z, q3.w};

    float ea[16];
#pragma unroll
    for (int k = 0; k < 16; ++k) ea[k] = 0.f;
#pragma unroll
    for (int d = 0; d < 16; ++d) {
        float vd = va[d];
#pragma unroll
        for (int k4 = 0; k4 < 4; ++k4) {
            float4 w = scW4[d * 4 + k4];
            ea[k4 * 4 + 0] += vd * w.x;
            ea[k4 * 4 + 1] += vd * w.y;
            ea[k4 * 4 + 2] += vd * w.z;
            ea[k4 * 4 + 3] += vd * w.w;
        }
    }
#pragma unroll
    for (int k = 0; k < 16; ++k) ea[k] = lrelu(ea[k]);

    float2 fi = g_ai[dst], fj = g_aj[src];
    float a0 = fi.x + fj.x + sae[et * 2 + 0];
    float a1 = fi.y + fj.y + sae[et * 2 + 1];
#pragma unroll
    for (int k = 0; k < 16; ++k) {
        float2 w = saW2[k];
        a0 += ea[k] * w.x;
        a1 += ea[k] * w.y;
    }
    float e0 = __expf(lrelu(a0));
    float e1 = __expf(lrelu(a1));

    // claim CSR slot, scatter record (5 x float4 = 80B contiguous)
    int pos = g_rowptr[dst] + atomicAdd(&g_cur[dst], 1);
    float4* rp = (float4*)(g_rec + (size_t)pos * RECF);
    rp[0] = make_float4(__int_as_float(src), e0, e1, ea[0]);
    rp[1] = make_float4(ea[1], ea[2], ea[3], ea[4]);
    rp[2] = make_float4(ea[5], ea[6], ea[7], ea[8]);
    rp[3] = make_float4(ea[9], ea[10], ea[11], ea[12]);
    rp[4] = make_float4(ea[13], ea[14], ea[15], 0.f);
}

// ---------------- K5: aggregate — warp per dst node ----------------
__global__ __launch_bounds__(256) void k_edge2(
    float* __restrict__ out, const float* __restrict__ linW, int n)
{
    __shared__ float slW2[512];     // lin_W rows 32..47 [16,32]
    __shared__ float ssa[8][32];    // staging for sacc transpose
    int tid = threadIdx.x;
    slW2[tid] = linW[1024 + tid];
    slW2[256 + tid] = linW[1280 + tid];
    __syncthreads();

    int w = threadIdx.x >> 5, lane = tid & 31;
    int node = blockIdx.x * 8 + w;
    if (node >= n) return;

    int beg = g_rowptr[node];
    int cnt = g_cnt[node];
    const float* rb = g_rec + (size_t)beg * RECF;

    float acc0 = 0.f, acc1 = 0.f;   // alpha-weighted hm sums (lane = col)
    float sacc = 0.f;               // lane<16: head0 sum(e0*ea[lane]); else head1
    float den0 = 0.f, den1 = 0.f;
    int ealane = 3 + (lane & 15);
    bool h1 = lane >= 16;

    int p = 0;
    for (; p + 2 <= cnt; p += 2) {
        float va = (lane < RECF) ? rb[(size_t)p * RECF + lane] : 0.f;
        float vb = (lane < RECF) ? rb[(size_t)(p + 1) * RECF + lane] : 0.f;

        int   sa = __float_as_int(__shfl_sync(0xffffffffu, va, 0));
        float a0 = __shfl_sync(0xffffffffu, va, 1);
        float a1 = __shfl_sync(0xffffffffu, va, 2);
        float aea = __shfl_sync(0xffffffffu, va, ealane);
        int   sb = __float_as_int(__shfl_sync(0xffffffffu, vb, 0));
        float b0 = __shfl_sync(0xffffffffu, vb, 1);
        float b1 = __shfl_sync(0xffffffffu, vb, 2);
        float bea = __shfl_sync(0xffffffffu, vb, ealane);

        float ha = g_hm[(size_t)sa * 32 + lane];
        float hb = g_hm[(size_t)sb * 32 + lane];
        acc0 += a0 * ha + b0 * hb;
        acc1 += a1 * ha + b1 * hb;
        sacc += (h1 ? a1 : a0) * aea + (h1 ? b1 : b0) * bea;
        den0 += a0 + b0;
        den1 += a1 + b1;
    }
    if (p < cnt) {
        float va = (lane < RECF) ? rb[(size_t)p * RECF + lane] : 0.f;
        int   sa = __float_as_int(__shfl_sync(0xffffffffu, va, 0));
        float a0 = __shfl_sync(0xffffffffu, va, 1);
        float a1 = __shfl_sync(0xffffffffu, va, 2);
        float aea = __shfl_sync(0xffffffffu, va, ealane);
        float ha = g_hm[(size_t)sa * 32 + lane];
        acc0 += a0 * ha;
        acc1 += a1 * ha;
        sacc += (h1 ? a1 : a0) * aea;
        den0 += a0;
        den1 += a1;
    }

    // fold sacc (per-head 16-dim ea aggregate) through lin_W2
    ssa[w][lane] = sacc;
    __syncwarp();
#pragma unroll
    for (int k = 0; k < 16; ++k) {
        float lw = slW2[k * 32 + lane];
        acc0 += ssa[w][k] * lw;
        acc1 += ssa[w][16 + k] * lw;
    }

    float i0 = (den0 != 0.f) ? 1.f / den0 : 0.f;
    float i1 = (den1 != 0.f) ? 1.f / den1 : 0.f;
    out[(size_t)node * 64 + lane]      = fmaxf(acc0 * i0, 0.f);
    out[(size_t)node * 64 + 32 + lane] = fmaxf(acc1 * i1, 0.f);
}

// ---------------- launch ----------------
extern "C" void kernel_launch(void* const* d_in, const int* in_sizes, int n_in,
                              void* d_out, int out_size)
{
    const float* x      = (const float*)d_in[0];
    const int*   ei     = (const int*)  d_in[1];
    const int*   ntypes = (const int*)  d_in[2];
    const int*   etypes = (const int*)  d_in[3];
    const float* eattr  = (const float*)d_in[4];
    const float* hetW   = (const float*)d_in[5];
    const float* hetB   = (const float*)d_in[6];
    const float* ett    = (const float*)d_in[7];
    const float* cW     = (const float*)d_in[8];
    const float* attW   = (const float*)d_in[9];
    const float* linW   = (const float*)d_in[10];

    int n = in_sizes[0] / 128;
    int e = in_sizes[1] / 2;
    if (n > NMAX) n = NMAX;
    if (e > EMAX) e = EMAX;

    k_zero<<<(n + 255) / 256, 256>>>(n);
    k_node<<<(n + 7) / 8, 256>>>(x, ntypes, hetW, hetB, attW, linW, n);
    k_ae<<<1, 32>>>(ett, attW);
    k_cnt<<<(e / 4 + 255) / 256, 256>>>(ei + e, e);

    int nb = (n + 1023) / 1024;
    k_scan1<<<nb, 1024>>>(n);
    k_scan2<<<1, 32>>>(nb);
    k_scan3<<<nb, 1024>>>(n);

    k_edge1<<<(e + 255) / 256, 256>>>(ei, etypes, eattr, cW, attW, e);
    k_edge2<<<(n + 7) / 8, 256>>>((float*)d_out, linW, n);
}

// round 4
// speedup vs baseline: 1.7935x; 1.1236x over previous
#include <cuda_runtime.h>
#include <cuda_fp16.h>
#include <cstdint>

#define NMAX 50000
#define EMAX 1600000
#define RECF 12   // floats per CSR record: src,e0,e1,pad, 8x half2 (ea[16] fp16)

// ---------------- scratch (static __device__, no allocations) ----------------
__device__ float  g_hm[NMAX * 32];            // h @ lin_W[0:32] per node (6.4MB, L2-resident)
__device__ float2 g_ai[NMAX];                 // h @ att_W[0:32]  (dst term)
__device__ float2 g_aj[NMAX];                 // h @ att_W[32:64] (src term)
__device__ float  g_rec[(size_t)EMAX * RECF]; // CSR records (76.8MB)
__device__ int    g_cnt4[4 * NMAX];           // split histogram
__device__ int    g_cnt[NMAX];
__device__ int    g_scan[NMAX];
__device__ int    g_rowptr[NMAX];
__device__ int    g_cur[NMAX];
__device__ int    g_bsum[128];
__device__ float  g_ae[8];                    // lrelu(etype_table) @ att_W[64:80]

__device__ __forceinline__ float lrelu(float v) { return v > 0.f ? v : 0.2f * v; }

// ---------------- K1: node precompute (warp per node) + zero + ae ----------------
__global__ __launch_bounds__(256) void k_node(
    const float* __restrict__ x, const int* __restrict__ ntypes,
    const float* __restrict__ hetW, const float* __restrict__ hetB,
    const float* __restrict__ attW, const float* __restrict__ linW,
    const float* __restrict__ ett, int n)
{
    __shared__ float sx[8][128];
    __shared__ float sh[8][32];
    int tid = threadIdx.x;

    // folded: zero split histogram
    int z = blockIdx.x * 256 + tid;
    if (z < 4 * n) g_cnt4[z] = 0;
    // folded: per-etype attention term
    if (blockIdx.x == 0 && tid < 8) {
        int t = tid >> 1, hh = tid & 1;
        float s = 0.f;
        for (int k = 0; k < 16; ++k)
            s += lrelu(ett[t * 16 + k]) * attW[(64 + k) * 2 + hh];
        g_ae[tid] = s;
    }

    int w = tid >> 5, lane = tid & 31;
    int node = blockIdx.x * 8 + w;
    if (node >= n) return;

    const float4* xr = (const float4*)(x + (size_t)node * 128);
    ((float4*)sx[w])[lane] = xr[lane];
    __syncwarp();

    int t = ntypes[node];
    const float* Wp = hetW + (size_t)t * 4096 + lane;
    float acc = hetB[t * 32 + lane];
#pragma unroll 16
    for (int d = 0; d < 128; ++d) acc += sx[w][d] * Wp[d * 32];
    float h = acc;
    sh[w][lane] = h;
    __syncwarp();

    float hm = 0.f;
#pragma unroll
    for (int k = 0; k < 32; ++k) hm += sh[w][k] * linW[k * 32 + lane];
    g_hm[(size_t)node * 32 + lane] = hm;

    float pi0 = h * attW[lane * 2 + 0];
    float pi1 = h * attW[lane * 2 + 1];
    float pj0 = h * attW[(32 + lane) * 2 + 0];
    float pj1 = h * attW[(32 + lane) * 2 + 1];
#pragma unroll
    for (int off = 16; off; off >>= 1) {
        pi0 += __shfl_down_sync(0xffffffffu, pi0, off);
        pi1 += __shfl_down_sync(0xffffffffu, pi1, off);
        pj0 += __shfl_down_sync(0xffffffffu, pj0, off);
        pj1 += __shfl_down_sync(0xffffffffu, pj1, off);
    }
    if (lane == 0) {
        g_ai[node] = make_float2(pi0, pi1);
        g_aj[node] = make_float2(pj0, pj1);
    }
}

// ---------------- K2: degree histogram, 4-way split counters ----------------
__global__ void k_cnt(const int* __restrict__ dst, int e_total, int n) {
    int i = blockIdx.x * 256 + threadIdx.x;
    int c = ((threadIdx.x >> 5) & 3) * n;
    int base = i * 4;
    if (base + 4 <= e_total) {
        int4 d = *(const int4*)(dst + base);
        atomicAdd(&g_cnt4[c + d.x], 1);
        atomicAdd(&g_cnt4[c + d.y], 1);
        atomicAdd(&g_cnt4[c + d.z], 1);
        atomicAdd(&g_cnt4[c + d.w], 1);
    } else {
        for (int e = base; e < e_total; ++e) atomicAdd(&g_cnt4[c + dst[e]], 1);
    }
}

// ---------------- K3: scan ----------------
__global__ void k_scan1(int n) {
    __shared__ int s[1024];
    int i = blockIdx.x * 1024 + threadIdx.x;
    int v = 0;
    if (i < n) {
        v = g_cnt4[i] + g_cnt4[n + i] + g_cnt4[2 * n + i] + g_cnt4[3 * n + i];
        g_cnt[i] = v;
    }
    s[threadIdx.x] = v;
    __syncthreads();
    for (int off = 1; off < 1024; off <<= 1) {
        int t = (threadIdx.x >= off) ? s[threadIdx.x - off] : 0;
        __syncthreads();
        s[threadIdx.x] += t;
        __syncthreads();
    }
    if (i < n) g_scan[i] = s[threadIdx.x];
    if (threadIdx.x == 1023) g_bsum[blockIdx.x] = s[1023];
}
__global__ void k_scan3(int n) {
    __shared__ int soff;
    int tid = threadIdx.x;
    if (tid < 32) {  // warp prefix over <=64 block sums
        int bid = blockIdx.x;
        int v = (tid < bid) ? g_bsum[tid] : 0;
        if (tid + 32 < bid) v += g_bsum[tid + 32];
#pragma unroll
        for (int off = 16; off; off >>= 1) v += __shfl_down_sync(0xffffffffu, v, off);
        if (tid == 0) soff = v;
    }
    __syncthreads();
    int i = blockIdx.x * 1024 + tid;
    if (i < n) {
        g_rowptr[i] = g_scan[i] - g_cnt[i] + soff;
        g_cur[i] = 0;
    }
}

// ---------------- K4: edge pass — ea, exp(alpha); scatter 48B record in CSR order ----------------
__global__ __launch_bounds__(256) void k_edge1(
    const int* __restrict__ ei, const int* __restrict__ etypes,
    const float* __restrict__ eattr, const float* __restrict__ cW,
    const float* __restrict__ attW, int e_total)
{
    __shared__ float4 scW4[64];
    __shared__ float2 saW2[16];
    __shared__ float  sae[8];
    int tid = threadIdx.x;
    if (tid < 64) scW4[tid] = ((const float4*)cW)[tid];
    else if (tid < 80) saW2[tid - 64] = ((const float2*)(attW + 160))[tid - 64];
    else if (tid < 88) sae[tid - 80] = g_ae[tid - 80];
    __syncthreads();

    int e = blockIdx.x * 256 + tid;
    if (e >= e_total) return;
    int src = ei[e], dst = ei[e_total + e], et = etypes[e];

    const float4* er = (const float4*)(eattr + (size_t)e * 16);
    float4 q0 = er[0], q1 = er[1], q2 = er[2], q3 = er[3];
    float va[16] = {q0.x, q0.y, q0.z, q0.w, q1.x, q1.y, q1.z, q1.w,
                    q2.x, q2.y, q2.z, q2.w, q3.x, q3.y, q3.z, q3.w};

    float ea[16];
#pragma unroll
    for (int k = 0; k < 16; ++k) ea[k] = 0.f;
#pragma unroll
    for (int d = 0; d < 16; ++d) {
        float vd = va[d];
#pragma unroll
        for (int k4 = 0; k4 < 4; ++k4) {
            float4 w = scW4[d * 4 + k4];
            ea[k4 * 4 + 0] += vd * w.x;
            ea[k4 * 4 + 1] += vd * w.y;
            ea[k4 * 4 + 2] += vd * w.z;
            ea[k4 * 4 + 3] += vd * w.w;
        }
    }
#pragma unroll
    for (int k = 0; k < 16; ++k) ea[k] = lrelu(ea[k]);

    float2 fi = g_ai[dst], fj = g_aj[src];
    float a0 = fi.x + fj.x + sae[et * 2 + 0];
    float a1 = fi.y + fj.y + sae[et * 2 + 1];
#pragma unroll
    for (int k = 0; k < 16; ++k) {
        float2 w = saW2[k];
        a0 += ea[k] * w.x;
        a1 += ea[k] * w.y;
    }
    float e0 = __expf(lrelu(a0));
    float e1 = __expf(lrelu(a1));

    // pack ea -> 8x half2
    uint32_t u[8];
#pragma unroll
    for (int i2 = 0; i2 < 8; ++i2) {
        __half2 h = __floats2half2_rn(ea[2 * i2], ea[2 * i2 + 1]);
        u[i2] = *reinterpret_cast<uint32_t*>(&h);
    }

    int pos = g_rowptr[dst] + atomicAdd(&g_cur[dst], 1);
    float4* rp = (float4*)(g_rec + (size_t)pos * RECF);
    rp[0] = make_float4(__int_as_float(src), e0, e1, 0.f);
    rp[1] = make_float4(__uint_as_float(u[0]), __uint_as_float(u[1]),
                        __uint_as_float(u[2]), __uint_as_float(u[3]));
    rp[2] = make_float4(__uint_as_float(u[4]), __uint_as_float(u[5]),
                        __uint_as_float(u[6]), __uint_as_float(u[7]));
}

// ---------------- K5: aggregate — warp per dst node ----------------
__global__ __launch_bounds__(256) void k_edge2(
    float* __restrict__ out, const float* __restrict__ linW, int n)
{
    __shared__ float slW2[512];     // lin_W rows 32..47 [16,32]
    __shared__ float ss0[8][32];    // head0 ea-aggregate staging
    __shared__ float ss1[8][32];    // head1
    int tid = threadIdx.x;
    slW2[tid] = linW[1024 + tid];
    slW2[256 + tid] = linW[1280 + tid];
    __syncthreads();

    int w = tid >> 5, lane = tid & 31;
    int node = blockIdx.x * 8 + w;
    if (node >= n) return;

    int beg = g_rowptr[node];
    int cnt = g_cnt[node];
    const float* rb = g_rec + (size_t)beg * RECF;

    float acc0 = 0.f, acc1 = 0.f;             // alpha-weighted hm sums (lane = col)
    float s0x = 0.f, s0y = 0.f, s1x = 0.f, s1y = 0.f;  // ea aggregates (lanes 4-11 A, 20-27 B)
    float den0 = 0.f, den1 = 0.f;

    // per-lane load offset: lanes 0-11 -> record p floats 0-11; lanes 16-27 -> record p+1
    int loff = (lane < 16) ? lane : (lane - 16) + RECF;
    bool lact = (lane & 15) < RECF;

    int p = 0;
#pragma unroll 2
    for (; p + 2 <= cnt; p += 2) {
        float v = lact ? rb[(size_t)p * RECF + loff] : 0.f;

        int   sa = __float_as_int(__shfl_sync(0xffffffffu, v, 0));
        float a0 = __shfl_sync(0xffffffffu, v, 1);
        float a1 = __shfl_sync(0xffffffffu, v, 2);
        int   sb = __float_as_int(__shfl_sync(0xffffffffu, v, 16));
        float b0 = __shfl_sync(0xffffffffu, v, 17);
        float b1 = __shfl_sync(0xffffffffu, v, 18);

        // ea halves: each lane 4-11 / 20-27 unpacks its own half2
        __half2 hh = *reinterpret_cast<__half2*>(&v);
        float2 f2 = __half22float2(hh);
        float e0s = (lane < 16) ? a0 : b0;
        float e1s = (lane < 16) ? a1 : b1;
        s0x += e0s * f2.x; s0y += e0s * f2.y;
        s1x += e1s * f2.x; s1y += e1s * f2.y;

        float ha = g_hm[(size_t)sa * 32 + lane];
        float hb = g_hm[(size_t)sb * 32 + lane];
        acc0 += a0 * ha + b0 * hb;
        acc1 += a1 * ha + b1 * hb;
        den0 += a0 + b0;
        den1 += a1 + b1;
    }
    if (p < cnt) {
        float v = (lane < RECF) ? rb[(size_t)p * RECF + lane] : 0.f;
        int   sa = __float_as_int(__shfl_sync(0xffffffffu, v, 0));
        float a0 = __shfl_sync(0xffffffffu, v, 1);
        float a1 = __shfl_sync(0xffffffffu, v, 2);
        __half2 hh = *reinterpret_cast<__half2*>(&v);
        float2 f2 = __half22float2(hh);
        if (lane < 16) {   // only A-half lanes accumulate
            s0x += a0 * f2.x; s0y += a0 * f2.y;
            s1x += a1 * f2.x; s1y += a1 * f2.y;
        }
        float ha = g_hm[(size_t)sa * 32 + lane];
        acc0 += a0 * ha;
        acc1 += a1 * ha;
        den0 += a0;
        den1 += a1;
    }

    // stage ea aggregates: dims 0-15 from lanes 4-11 (A-half) and 20-27 (B-half)
    if (lane >= 4 && lane < 12) {
        int d = (lane - 4) * 2;
        ss0[w][d] = s0x; ss0[w][d + 1] = s0y;
        ss1[w][d] = s1x; ss1[w][d + 1] = s1y;
    } else if (lane >= 20 && lane < 28) {
        int d = 16 + (lane - 20) * 2;
        ss0[w][d] = s0x; ss0[w][d + 1] = s0y;
        ss1[w][d] = s1x; ss1[w][d + 1] = s1y;
    }
    __syncwarp();

#pragma unroll
    for (int k = 0; k < 16; ++k) {
        float lw = slW2[k * 32 + lane];
        acc0 += (ss0[w][k] + ss0[w][16 + k]) * lw;
        acc1 += (ss1[w][k] + ss1[w][16 + k]) * lw;
    }

    float i0 = (den0 != 0.f) ? 1.f / den0 : 0.f;
    float i1 = (den1 != 0.f) ? 1.f / den1 : 0.f;
    out[(size_t)node * 64 + lane]      = fmaxf(acc0 * i0, 0.f);
    out[(size_t)node * 64 + 32 + lane] = fmaxf(acc1 * i1, 0.f);
}

// ---------------- launch ----------------
extern "C" void kernel_launch(void* const* d_in, const int* in_sizes, int n_in,
                              void* d_out, int out_size)
{
    const float* x      = (const float*)d_in[0];
    const int*   ei     = (const int*)  d_in[1];
    const int*   ntypes = (const int*)  d_in[2];
    const int*   etypes = (const int*)  d_in[3];
    const float* eattr  = (const float*)d_in[4];
    const float* hetW   = (const float*)d_in[5];
    const float* hetB   = (const float*)d_in[6];
    const float* ett    = (const float*)d_in[7];
    const float* cW     = (const float*)d_in[8];
    const float* attW   = (const float*)d_in[9];
    const float* linW   = (const float*)d_in[10];

    int n = in_sizes[0] / 128;
    int e = in_sizes[1] / 2;
    if (n > NMAX) n = NMAX;
    if (e > EMAX) e = EMAX;

    k_node<<<(n + 7) / 8, 256>>>(x, ntypes, hetW, hetB, attW, linW, ett, n);
    k_cnt<<<(e / 4 + 255) / 256, 256>>>(ei + e, e, n);

    int nb = (n + 1023) / 1024;
    k_scan1<<<nb, 1024>>>(n);
    k_scan3<<<nb, 1024>>>(n);

    k_edge1<<<(e + 255) / 256, 256>>>(ei, etypes, eattr, cW, attW, e);
    k_edge2<<<(n + 7) / 8, 256>>>((float*)d_out, linW, n);
}